// round 12
// baseline (speedup 1.0000x reference)
#include <cuda_runtime.h>
#include <cuda_bf16.h>
#include <stdint.h>

#define N_NODES 100000
#define N_EDGES 1200000
#define D 64

// Persistent scratch: agg = scatter_sum(relu(x[src] + e)); zeroed by memset.
__device__ __align__(16) float g_agg[(size_t)N_NODES * D];

// ---------------------------------------------------------------------------
// f32x2 packed-FMA helpers (FFMA2 — PTX-only, sm_100+)
// ---------------------------------------------------------------------------
__device__ __forceinline__ unsigned long long pk2(float lo, float hi) {
    unsigned long long r;
    asm("mov.b64 %0, {%1, %2};" : "=l"(r) : "f"(lo), "f"(hi));
    return r;
}
__device__ __forceinline__ unsigned long long ffma2(unsigned long long a,
                                                    unsigned long long b,
                                                    unsigned long long c) {
    unsigned long long d;
    asm("fma.rn.f32x2 %0, %1, %2, %3;" : "=l"(d) : "l"(a), "l"(b), "l"(c));
    return d;
}
__device__ __forceinline__ void upk2(unsigned long long v, float& lo, float& hi) {
    asm("mov.b64 {%0, %1}, %2;" : "=f"(lo), "=f"(hi) : "l"(v));
}

// ---------------------------------------------------------------------------
// Kernel 1: per-edge message + scatter reduce (L2-transit bound, unchanged).
// ---------------------------------------------------------------------------
__global__ void edge_kernel(const float* __restrict__ x,
                            const int* __restrict__ ei,
                            const float* __restrict__ ea) {
    int t = blockIdx.x * blockDim.x + threadIdx.x;
    const int total = N_EDGES * 16;
    if (t >= total) return;
    int e = t >> 4;
    int c = t & 15;

    int src = __ldg(ei + e);
    int dst = __ldg(ei + N_EDGES + e);

    float4 xv = __ldg(reinterpret_cast<const float4*>(x) + (size_t)src * (D / 4) + c);
    float4 ev = __ldcs(reinterpret_cast<const float4*>(ea) + (size_t)e * (D / 4) + c);

    float4 m;
    m.x = fmaxf(xv.x + ev.x, 0.0f);
    m.y = fmaxf(xv.y + ev.y, 0.0f);
    m.z = fmaxf(xv.z + ev.z, 0.0f);
    m.w = fmaxf(xv.w + ev.w, 0.0f);

    float* p = g_agg + (size_t)dst * D + c * 4;
    asm volatile("red.global.add.v4.f32 [%0], {%1, %2, %3, %4};"
                 :: "l"(p), "f"(m.x), "f"(m.y), "f"(m.z), "f"(m.w)
                 : "memory");
}

// ---------------------------------------------------------------------------
// Kernel 2: tiled MLP.  out = relu((x+agg) @ W1 + b1) @ W2 + b2
//
// Block = 256 threads, TILE_N = 128 nodes. Thread owns 4 nodes x 8 cols
// (cols cg*4..+3 and 32+cg*4..+3). Per k: 3 LDS.128 feed 16 FFMA2 + 4 packs.
//   hv: hsT[k][ng*4..+3] — 4 distinct 16B chunks/warp, contiguous 64B,
//       broadcast 8-way, conflict-free.
//   wp: W row k, 8 distinct 16B chunks = full 128B row, conflict-free.
// __launch_bounds__(256,3): 3 blocks/SM = 768 threads (6 warps/SMSP) to
// cover LDS latency; smem 50 KB/block (hsT + one W buffer, W2 reloaded).
// ---------------------------------------------------------------------------
#define TILE_N 128
#define HT_PAD 132
#define SMEM_HST_FLOATS (D * HT_PAD)             // 8448
#define SMEM_TOTAL_BYTES ((SMEM_HST_FLOATS + D * D) * 4)   // 50176

extern __shared__ float smem_dyn[];

// acc[n][p]: node ng*4+n; p=0,1 -> cols (cg*4+0,+1),(cg*4+2,+3);
//            p=2,3 -> (32+cg*4+0,+1),(32+cg*4+2,+3)
__device__ __forceinline__ void gemm_pass(const float* hsT, const float* Ws,
                                          int ng, int cg,
                                          unsigned long long acc[4][4]) {
    #pragma unroll 8
    for (int k = 0; k < D; ++k) {
        float4 hv = *reinterpret_cast<const float4*>(hsT + k * HT_PAD + ng * 4);
        ulonglong2 wp0 = *reinterpret_cast<const ulonglong2*>(Ws + k * D + cg * 4);
        ulonglong2 wp1 = *reinterpret_cast<const ulonglong2*>(Ws + k * D + 32 + cg * 4);

        unsigned long long h0 = pk2(hv.x, hv.x);
        unsigned long long h1 = pk2(hv.y, hv.y);
        unsigned long long h2 = pk2(hv.z, hv.z);
        unsigned long long h3 = pk2(hv.w, hv.w);

        acc[0][0] = ffma2(h0, wp0.x, acc[0][0]);
        acc[0][1] = ffma2(h0, wp0.y, acc[0][1]);
        acc[0][2] = ffma2(h0, wp1.x, acc[0][2]);
        acc[0][3] = ffma2(h0, wp1.y, acc[0][3]);
        acc[1][0] = ffma2(h1, wp0.x, acc[1][0]);
        acc[1][1] = ffma2(h1, wp0.y, acc[1][1]);
        acc[1][2] = ffma2(h1, wp1.x, acc[1][2]);
        acc[1][3] = ffma2(h1, wp1.y, acc[1][3]);
        acc[2][0] = ffma2(h2, wp0.x, acc[2][0]);
        acc[2][1] = ffma2(h2, wp0.y, acc[2][1]);
        acc[2][2] = ffma2(h2, wp1.x, acc[2][2]);
        acc[2][3] = ffma2(h2, wp1.y, acc[2][3]);
        acc[3][0] = ffma2(h3, wp0.x, acc[3][0]);
        acc[3][1] = ffma2(h3, wp0.y, acc[3][1]);
        acc[3][2] = ffma2(h3, wp1.x, acc[3][2]);
        acc[3][3] = ffma2(h3, wp1.y, acc[3][3]);
    }
}

__global__ void __launch_bounds__(256, 3)
mlp_kernel(const float* __restrict__ x,
           const float* __restrict__ W1, const float* __restrict__ b1,
           const float* __restrict__ W2, const float* __restrict__ b2,
           float* __restrict__ out) {
    float* hsT = smem_dyn;                       // [D][HT_PAD]
    float* Ws  = smem_dyn + SMEM_HST_FLOATS;     // [D][D]

    const int tid = threadIdx.x;
    const int node0 = blockIdx.x * TILE_N;
    const int cg = tid & 7;          // col group (0..7)
    const int ng = tid >> 3;         // node group (0..31), 4 nodes each

    // Stage W1.
    {
        const float4* wg = reinterpret_cast<const float4*>(W1);
        float4* ws = reinterpret_cast<float4*>(Ws);
        #pragma unroll
        for (int i = tid; i < D * D / 4; i += 256) ws[i] = wg[i];
    }
    // Stage h tile = x + agg, transposed into hsT[k][n]. Tail: clamp node.
    {
        const float4* ag = reinterpret_cast<const float4*>(g_agg);
        const float4* xg = reinterpret_cast<const float4*>(x);
        #pragma unroll
        for (int i = tid; i < TILE_N * (D / 4); i += 256) {
            int n = i >> 4;          // node within tile
            int c = i & 15;          // float4 chunk
            int node = node0 + n;
            if (node >= N_NODES) node = N_NODES - 1;
            size_t gi = (size_t)node * (D / 4) + c;
            float4 a = ag[gi];
            float4 v = __ldg(xg + gi);
            a.x += v.x; a.y += v.y; a.z += v.z; a.w += v.w;
            hsT[(c * 4 + 0) * HT_PAD + n] = a.x;
            hsT[(c * 4 + 1) * HT_PAD + n] = a.y;
            hsT[(c * 4 + 2) * HT_PAD + n] = a.z;
            hsT[(c * 4 + 3) * HT_PAD + n] = a.w;
        }
    }
    __syncthreads();

    // Bias pairs for this thread's 8 cols.
    float4 b1a = __ldg(reinterpret_cast<const float4*>(b1) + cg);
    float4 b1b = __ldg(reinterpret_cast<const float4*>(b1) + 8 + cg);
    float4 b2a = __ldg(reinterpret_cast<const float4*>(b2) + cg);
    float4 b2b = __ldg(reinterpret_cast<const float4*>(b2) + 8 + cg);

    unsigned long long acc[4][4];

    // ---- Layer 1: t = relu(h @ W1 + b1) ----
    {
        unsigned long long i0 = pk2(b1a.x, b1a.y), i1 = pk2(b1a.z, b1a.w);
        unsigned long long i2 = pk2(b1b.x, b1b.y), i3 = pk2(b1b.z, b1b.w);
        #pragma unroll
        for (int n = 0; n < 4; ++n) {
            acc[n][0] = i0; acc[n][1] = i1; acc[n][2] = i2; acc[n][3] = i3;
        }
    }
    gemm_pass(hsT, Ws, ng, cg, acc);

    __syncthreads();   // done reading hsT + Ws(W1); acc holds results

    // Unpack+relu+write t back transposed, directly from packed acc.
    #pragma unroll
    for (int p = 0; p < 4; ++p) {
        int colbase = (p < 2) ? (cg * 4 + p * 2) : (32 + cg * 4 + (p - 2) * 2);
        float lo0, hi0, lo1, hi1, lo2, hi2, lo3, hi3;
        upk2(acc[0][p], lo0, hi0);
        upk2(acc[1][p], lo1, hi1);
        upk2(acc[2][p], lo2, hi2);
        upk2(acc[3][p], lo3, hi3);
        float4 vlo = make_float4(fmaxf(lo0, 0.f), fmaxf(lo1, 0.f),
                                 fmaxf(lo2, 0.f), fmaxf(lo3, 0.f));
        float4 vhi = make_float4(fmaxf(hi0, 0.f), fmaxf(hi1, 0.f),
                                 fmaxf(hi2, 0.f), fmaxf(hi3, 0.f));
        *reinterpret_cast<float4*>(&hsT[(colbase + 0) * HT_PAD + ng * 4]) = vlo;
        *reinterpret_cast<float4*>(&hsT[(colbase + 1) * HT_PAD + ng * 4]) = vhi;
    }
    // Reload Ws with W2.
    {
        const float4* wg = reinterpret_cast<const float4*>(W2);
        float4* ws = reinterpret_cast<float4*>(Ws);
        #pragma unroll
        for (int i = tid; i < D * D / 4; i += 256) ws[i] = wg[i];
    }
    __syncthreads();

    // ---- Layer 2: out = t @ W2 + b2 ----
    {
        unsigned long long i0 = pk2(b2a.x, b2a.y), i1 = pk2(b2a.z, b2a.w);
        unsigned long long i2 = pk2(b2b.x, b2b.y), i3 = pk2(b2b.z, b2b.w);
        #pragma unroll
        for (int n = 0; n < 4; ++n) {
            acc[n][0] = i0; acc[n][1] = i1; acc[n][2] = i2; acc[n][3] = i3;
        }
    }
    gemm_pass(hsT, Ws, ng, cg, acc);

    float4* ob = reinterpret_cast<float4*>(out);
    #pragma unroll
    for (int n = 0; n < 4; ++n) {
        int node = node0 + ng * 4 + n;
        if (node < N_NODES) {
            float a, b, c, d2;
            upk2(acc[n][0], a, b); upk2(acc[n][1], c, d2);
            ob[(size_t)node * (D / 4) + cg] = make_float4(a, b, c, d2);
            upk2(acc[n][2], a, b); upk2(acc[n][3], c, d2);
            ob[(size_t)node * (D / 4) + 8 + cg] = make_float4(a, b, c, d2);
        }
    }
}

// ---------------------------------------------------------------------------
// Launch.
// ---------------------------------------------------------------------------
extern "C" void kernel_launch(void* const* d_in, const int* in_sizes, int n_in,
                              void* d_out, int out_size) {
    const float* x   = (const float*)d_in[0];
    const int*   ei  = (const int*)d_in[1];
    const float* ea  = (const float*)d_in[2];
    const float* W1  = (const float*)d_in[3];
    const float* b1  = (const float*)d_in[4];
    const float* W2  = (const float*)d_in[5];
    const float* b2  = (const float*)d_in[6];
    float*       out = (float*)d_out;

    // agg <- 0 (graph-capturable)
    void* aggp = nullptr;
    cudaGetSymbolAddress(&aggp, g_agg);
    cudaMemsetAsync(aggp, 0, sizeof(float) * (size_t)N_NODES * D);

    {   // scatter-sum messages
        int total = N_EDGES * 16;
        edge_kernel<<<(total + 255) / 256, 256>>>(x, ei, ea);
    }
    {   // fused (x+agg) -> MLP; 782 blocks (tail guarded)
        static bool attr_set = false;
        if (!attr_set) {
            cudaFuncSetAttribute(mlp_kernel,
                                 cudaFuncAttributeMaxDynamicSharedMemorySize,
                                 SMEM_TOTAL_BYTES);
            attr_set = true;
        }
        int grid = (N_NODES + TILE_N - 1) / TILE_N;
        mlp_kernel<<<grid, 256, SMEM_TOTAL_BYTES>>>(x, W1, b1, W2, b2, out);
    }
}